// round 12
// baseline (speedup 1.0000x reference)
#include <cuda_runtime.h>
#include <cuda_bf16.h>
#include <cstdint>

#define N_EMBD 1024
#define N_HEAD 16
#define HEAD_DIM 64
#define BATCH 4
#define SEQ 2048
#define C3 (3 * N_EMBD)

// Scratch (no cudaMalloc allowed)
__device__ float g_qkv[BATCH * SEQ * C3];      // ~100.7 MB
__device__ float g_att[BATCH * SEQ * N_EMBD];  // ~33.6 MB

__device__ __forceinline__ uint32_t f2tf32(float x) {
    uint32_t r;
    asm("cvt.rna.tf32.f32 %0, %1;" : "=r"(r) : "f"(x));
    return r;
}

__device__ __forceinline__ void mma_tf32(float c[4], uint32_t a0, uint32_t a1,
                                         uint32_t a2, uint32_t a3,
                                         uint32_t b0, uint32_t b1) {
    asm volatile(
        "mma.sync.aligned.m16n8k8.row.col.f32.tf32.tf32.f32 "
        "{%0,%1,%2,%3}, {%4,%5,%6,%7}, {%8,%9}, {%0,%1,%2,%3};"
        : "+f"(c[0]), "+f"(c[1]), "+f"(c[2]), "+f"(c[3])
        : "r"(a0), "r"(a1), "r"(a2), "r"(a3), "r"(b0), "r"(b1));
}

__device__ __forceinline__ void mma_bf16(float c[4], uint32_t a0, uint32_t a1,
                                         uint32_t a2, uint32_t a3,
                                         uint32_t b0, uint32_t b1) {
    asm volatile(
        "mma.sync.aligned.m16n8k16.row.col.f32.bf16.bf16.f32 "
        "{%0,%1,%2,%3}, {%4,%5,%6,%7}, {%8,%9}, {%0,%1,%2,%3};"
        : "+f"(c[0]), "+f"(c[1]), "+f"(c[2]), "+f"(c[3])
        : "r"(a0), "r"(a1), "r"(a2), "r"(a3), "r"(b0), "r"(b1));
}

// pack two floats -> bf16x2 (x in low half = even k element)
__device__ __forceinline__ uint32_t pack_bf16(float x, float y) {
    __nv_bfloat162 h = __floats2bfloat162_rn(x, y);
    return *(uint32_t*)&h;
}

// ---------------------------------------------------------------------------
// tf32 tensor-core GEMM with bias (proven round-9 version: single-buffered,
// static smem, regs<=124 -> 2 blocks/SM).
// ---------------------------------------------------------------------------
#define BM 128
#define BN 128
#define BKT 32

__global__ __launch_bounds__(256) void gemm_tf32_bias(
    const float* __restrict__ A, const float* __restrict__ B,
    const float* __restrict__ bias, float* __restrict__ C,
    int M, int N, int K)
{
    __shared__ uint32_t As[BM][36];
    __shared__ uint32_t Bs[BKT][136];

    const int tid = threadIdx.x;
    const int wid = tid >> 5, lane = tid & 31;
    const int wm = wid & 3, wn = wid >> 2;
    const int tg = lane & 3, grp = lane >> 2;
    const int row0 = blockIdx.y * BM, col0 = blockIdx.x * BN;

    const int arow = tid >> 3;
    const int acol = (tid & 7) * 4;
    const int brow = tid >> 5;
    const int bcol = (tid & 31) * 4;

    const float* Ap = A + (long)(row0 + arow) * K + acol;
    const float* Bp = B + (long)brow * N + col0 + bcol;

    float acc[2][8][4];
    #pragma unroll
    for (int mi = 0; mi < 2; mi++)
        #pragma unroll
        for (int ni = 0; ni < 8; ni++)
            #pragma unroll
            for (int e = 0; e < 4; e++) acc[mi][ni][e] = 0.0f;

    float4 ra[4], rb[4];
    const int nt = K / BKT;

    #pragma unroll
    for (int p = 0; p < 4; p++) {
        ra[p] = *(const float4*)(Ap + (long)(p * 32) * K);
        rb[p] = *(const float4*)(Bp + (long)(p * 8) * N);
    }

    for (int t = 0; t < nt; t++) {
        #pragma unroll
        for (int p = 0; p < 4; p++) {
            As[arow + p * 32][acol + 0] = f2tf32(ra[p].x);
            As[arow + p * 32][acol + 1] = f2tf32(ra[p].y);
            As[arow + p * 32][acol + 2] = f2tf32(ra[p].z);
            As[arow + p * 32][acol + 3] = f2tf32(ra[p].w);
            Bs[brow + p * 8][bcol + 0] = f2tf32(rb[p].x);
            Bs[brow + p * 8][bcol + 1] = f2tf32(rb[p].y);
            Bs[brow + p * 8][bcol + 2] = f2tf32(rb[p].z);
            Bs[brow + p * 8][bcol + 3] = f2tf32(rb[p].w);
        }
        __syncthreads();

        if (t + 1 < nt) {
            #pragma unroll
            for (int p = 0; p < 4; p++) {
                ra[p] = *(const float4*)(Ap + (long)(p * 32) * K + (t + 1) * BKT);
                rb[p] = *(const float4*)(Bp + (long)((t + 1) * BKT + p * 8) * N);
            }
        }

        #pragma unroll
        for (int ks = 0; ks < 4; ks++) {
            const int kb = ks * 8;
            uint32_t af[2][4];
            #pragma unroll
            for (int mi = 0; mi < 2; mi++) {
                const int ab = wm * 32 + mi * 16;
                af[mi][0] = As[ab + grp][kb + tg];
                af[mi][1] = As[ab + grp + 8][kb + tg];
                af[mi][2] = As[ab + grp][kb + tg + 4];
                af[mi][3] = As[ab + grp + 8][kb + tg + 4];
            }
            #pragma unroll
            for (int ni = 0; ni < 8; ni++) {
                const int nb = wn * 64 + ni * 8 + grp;
                uint32_t b0 = Bs[kb + tg][nb];
                uint32_t b1 = Bs[kb + tg + 4][nb];
                #pragma unroll
                for (int mi = 0; mi < 2; mi++)
                    mma_tf32(acc[mi][ni], af[mi][0], af[mi][1], af[mi][2],
                             af[mi][3], b0, b1);
            }
        }
        __syncthreads();
    }

    #pragma unroll
    for (int mi = 0; mi < 2; mi++) {
        const long r0 = row0 + wm * 32 + mi * 16 + grp;
        const long r1 = r0 + 8;
        #pragma unroll
        for (int ni = 0; ni < 8; ni++) {
            const int c = col0 + wn * 64 + ni * 8 + tg * 2;
            const float bv0 = __ldg(&bias[c]);
            const float bv1 = __ldg(&bias[c + 1]);
            float2 o0 = make_float2(acc[mi][ni][0] + bv0, acc[mi][ni][1] + bv1);
            float2 o1 = make_float2(acc[mi][ni][2] + bv0, acc[mi][ni][3] + bv1);
            *(float2*)&C[r0 * N + c] = o0;
            *(float2*)&C[r1 * N + c] = o1;
        }
    }
}

// ---------------------------------------------------------------------------
// Tensor-core flash attention (causal). One block = (b, h, 64-row q-tile).
// 128 threads = 4 warps, each warp owns 16 q rows.
// S = Q K^T via bf16 m16n8k16 hi/lo 3-mma (qh*kh + qh*kl + ql*kh), which
// halves the S mma-instruction count vs tf32 k8. K hi/lo packed per bf16-pair
// into one uint2 -> one LDS.64 per B fragment (conflict-free at stride 36u2).
// O = P V via tf32 k8 mma, P relayout via intra-warp shuffles (round-9).
// Smem: Kc 18.4 KB + Vs 18.4 KB = 36.9 KB.
// ---------------------------------------------------------------------------
#define QT 64
#define KTILE 64
#define KC_S 36   // uint2 stride (72 words) -> 8*grp mod 32 octets, conflict-free
#define VS_S 72
#define ATT_SMEM ((64 * KC_S * 2 + 64 * VS_S) * 4)  // 36864 B

__global__ __launch_bounds__(128) void flash_attn_tc(
    const float* __restrict__ qkv, float* __restrict__ y)
{
    extern __shared__ __align__(16) float sm[];
    uint2* Kc = (uint2*)sm;                 // [64][36] {bf16x2 hi, bf16x2 lo}
    float* Vs = sm + 64 * KC_S * 2;         // [64][72] tf32 bits

    const int qt = blockIdx.x, h = blockIdx.y, b = blockIdx.z;
    const int tid = threadIdx.x;
    const int w = tid >> 5, lane = tid & 31;
    const int grp = lane >> 2, tg = lane & 3;
    const int row0 = qt * QT;
    const long base = (long)b * SEQ * C3;
    const int hoff = h * HEAD_DIM;

    // --- Q fragments (scaled by 1/8), bf16 hi/lo, packed pairs, registers ---
    // m16n8k16 A layout: a0=(row grp, k 2tg,2tg+1) a1=(row grp+8) a2=(row grp, k+8) a3=(row grp+8, k+8)
    uint32_t qhi[4][4], qlo[4][4];
    {
        const float* qA = qkv + base + (long)(row0 + 16 * w + grp) * C3 + hoff;
        const float* qB = qA + 8 * C3;
        #pragma unroll
        for (int ks = 0; ks < 4; ks++) {
            const int k0 = ks * 16 + 2 * tg;
            float fa0 = qA[k0] * 0.125f,     fa1 = qA[k0 + 1] * 0.125f;
            float fb0 = qB[k0] * 0.125f,     fb1 = qB[k0 + 1] * 0.125f;
            float fa2 = qA[k0 + 8] * 0.125f, fa3 = qA[k0 + 9] * 0.125f;
            float fb2 = qB[k0 + 8] * 0.125f, fb3 = qB[k0 + 9] * 0.125f;
            float ha0 = __bfloat162float(__float2bfloat16_rn(fa0));
            float ha1 = __bfloat162float(__float2bfloat16_rn(fa1));
            float hb0 = __bfloat162float(__float2bfloat16_rn(fb0));
            float hb1 = __bfloat162float(__float2bfloat16_rn(fb1));
            float ha2 = __bfloat162float(__float2bfloat16_rn(fa2));
            float ha3 = __bfloat162float(__float2bfloat16_rn(fa3));
            float hb2 = __bfloat162float(__float2bfloat16_rn(fb2));
            float hb3 = __bfloat162float(__float2bfloat16_rn(fb3));
            qhi[ks][0] = pack_bf16(ha0, ha1);
            qhi[ks][1] = pack_bf16(hb0, hb1);
            qhi[ks][2] = pack_bf16(ha2, ha3);
            qhi[ks][3] = pack_bf16(hb2, hb3);
            qlo[ks][0] = pack_bf16(fa0 - ha0, fa1 - ha1);
            qlo[ks][1] = pack_bf16(fb0 - hb0, fb1 - hb1);
            qlo[ks][2] = pack_bf16(fa2 - ha2, fa3 - ha3);
            qlo[ks][3] = pack_bf16(fb2 - hb2, fb3 - hb3);
        }
    }

    float oacc[8][4];
    #pragma unroll
    for (int ni = 0; ni < 8; ni++)
        #pragma unroll
        for (int e = 0; e < 4; e++) oacc[ni][e] = 0.0f;
    float mA = -1e30f, mB = -1e30f, lA = 0.0f, lB = 0.0f;

    for (int kt = 0; kt <= qt; kt++) {
        const int kc0 = kt * KTILE;
        __syncthreads();  // prior tile's smem reads done

        // K tile: bf16 hi/lo packed pairs. warp-uniform row per pass,
        // p = lane -> coalesced float2 global loads, conflict-free STS.64.
        #pragma unroll
        for (int i = 0; i < 16; i++) {
            const int e = tid + i * 128;
            const int r = e >> 5, p = e & 31;
            const float2 kv = *(const float2*)(qkv + base + (long)(kc0 + r) * C3 +
                                               hoff + N_EMBD + 2 * p);
            const float h0 = __bfloat162float(__float2bfloat16_rn(kv.x));
            const float h1 = __bfloat162float(__float2bfloat16_rn(kv.y));
            uint2 val;
            val.x = pack_bf16(h0, h1);
            val.y = pack_bf16(kv.x - h0, kv.y - h1);
            Kc[r * KC_S + p] = val;
        }
        // V tile (tf32 bits)
        #pragma unroll
        for (int i = 0; i < 8; i++) {
            const int e = tid + i * 128;
            const int r = e >> 4, c4 = (e & 15) * 4;
            const float4 vv = *(const float4*)(qkv + base + (long)(kc0 + r) * C3 +
                                               hoff + 2 * N_EMBD + c4);
            float4 vt;
            vt.x = __uint_as_float(f2tf32(vv.x));
            vt.y = __uint_as_float(f2tf32(vv.y));
            vt.z = __uint_as_float(f2tf32(vv.z));
            vt.w = __uint_as_float(f2tf32(vv.w));
            *(float4*)&Vs[r * VS_S + c4] = vt;
        }
        __syncthreads();

        // --- S = Q K^T (bf16 hi/lo compensated, k16) ---
        float sacc[8][4];
        #pragma unroll
        for (int ni = 0; ni < 8; ni++)
            #pragma unroll
            for (int e = 0; e < 4; e++) sacc[ni][e] = 0.0f;

        #pragma unroll
        for (int ks = 0; ks < 4; ks++) {
            #pragma unroll
            for (int ni = 0; ni < 8; ni++) {
                const int nb = ni * 8 + grp;
                const uint2 p0 = Kc[nb * KC_S + ks * 8 + tg];      // b0: {hi, lo}
                const uint2 p1 = Kc[nb * KC_S + ks * 8 + 4 + tg];  // b1: {hi, lo}
                mma_bf16(sacc[ni], qhi[ks][0], qhi[ks][1], qhi[ks][2], qhi[ks][3], p0.x, p1.x);
                mma_bf16(sacc[ni], qhi[ks][0], qhi[ks][1], qhi[ks][2], qhi[ks][3], p0.y, p1.y);
                mma_bf16(sacc[ni], qlo[ks][0], qlo[ks][1], qlo[ks][2], qlo[ks][3], p0.x, p1.x);
            }
        }

        // causal mask (diagonal tile only)
        if (kt == qt) {
            const int rA = row0 + 16 * w + grp, rB = rA + 8;
            #pragma unroll
            for (int ni = 0; ni < 8; ni++) {
                const int c0 = kc0 + ni * 8 + 2 * tg;
                if (c0 > rA) sacc[ni][0] = -1e30f;
                if (c0 + 1 > rA) sacc[ni][1] = -1e30f;
                if (c0 > rB) sacc[ni][2] = -1e30f;
                if (c0 + 1 > rB) sacc[ni][3] = -1e30f;
            }
        }

        // --- online softmax (rows grp and grp+8) ---
        float mtA = sacc[0][0], mtB = sacc[0][2];
        #pragma unroll
        for (int ni = 0; ni < 8; ni++) {
            mtA = fmaxf(mtA, fmaxf(sacc[ni][0], sacc[ni][1]));
            mtB = fmaxf(mtB, fmaxf(sacc[ni][2], sacc[ni][3]));
        }
        mtA = fmaxf(mtA, __shfl_xor_sync(0xffffffffu, mtA, 1));
        mtA = fmaxf(mtA, __shfl_xor_sync(0xffffffffu, mtA, 2));
        mtB = fmaxf(mtB, __shfl_xor_sync(0xffffffffu, mtB, 1));
        mtB = fmaxf(mtB, __shfl_xor_sync(0xffffffffu, mtB, 2));

        const float mnA = fmaxf(mA, mtA), mnB = fmaxf(mB, mtB);
        const float cA = __expf(mA - mnA), cB = __expf(mB - mnB);
        mA = mnA; mB = mnB;
        lA *= cA; lB *= cB;
        #pragma unroll
        for (int ni = 0; ni < 8; ni++) {
            oacc[ni][0] *= cA; oacc[ni][1] *= cA;
            oacc[ni][2] *= cB; oacc[ni][3] *= cB;
        }

        // exp -> probabilities (tf32 bits, accumulator layout, registers)
        uint32_t up[8][4];
        float sumA = 0.0f, sumB = 0.0f;
        #pragma unroll
        for (int ni = 0; ni < 8; ni++) {
            const float p0 = __expf(sacc[ni][0] - mA);
            const float p1 = __expf(sacc[ni][1] - mA);
            const float p2 = __expf(sacc[ni][2] - mB);
            const float p3 = __expf(sacc[ni][3] - mB);
            sumA += p0 + p1; sumB += p2 + p3;
            up[ni][0] = f2tf32(p0); up[ni][1] = f2tf32(p1);
            up[ni][2] = f2tf32(p2); up[ni][3] = f2tf32(p3);
        }
        lA += sumA; lB += sumB;

        // --- O += P V: A-fragments of P via intra-warp shuffles (tf32 k8) ---
        const int src0 = (lane & ~3) | (tg >> 1);
        const int src2 = src0 | 2;
        const bool odd = (tg & 1) != 0;
        #pragma unroll
        for (int ks = 0; ks < 8; ks++) {
            const int kb = ks * 8;
            const uint32_t w00 = __shfl_sync(0xffffffffu, up[ks][0], src0);
            const uint32_t w01 = __shfl_sync(0xffffffffu, up[ks][1], src0);
            const uint32_t w02 = __shfl_sync(0xffffffffu, up[ks][2], src0);
            const uint32_t w03 = __shfl_sync(0xffffffffu, up[ks][3], src0);
            const uint32_t w20 = __shfl_sync(0xffffffffu, up[ks][0], src2);
            const uint32_t w21 = __shfl_sync(0xffffffffu, up[ks][1], src2);
            const uint32_t w22 = __shfl_sync(0xffffffffu, up[ks][2], src2);
            const uint32_t w23 = __shfl_sync(0xffffffffu, up[ks][3], src2);
            const uint32_t a0 = odd ? w01 : w00;
            const uint32_t a1 = odd ? w03 : w02;
            const uint32_t a2 = odd ? w21 : w20;
            const uint32_t a3 = odd ? w23 : w22;
            #pragma unroll
            for (int ni = 0; ni < 8; ni++) {
                const uint32_t b0 = __float_as_uint(Vs[(kb + tg) * VS_S + ni * 8 + grp]);
                const uint32_t b1 = __float_as_uint(Vs[(kb + tg + 4) * VS_S + ni * 8 + grp]);
                mma_tf32(oacc[ni], a0, a1, a2, a3, b0, b1);
            }
        }
    }

    // --- finalize ---
    lA += __shfl_xor_sync(0xffffffffu, lA, 1);
    lA += __shfl_xor_sync(0xffffffffu, lA, 2);
    lB += __shfl_xor_sync(0xffffffffu, lB, 1);
    lB += __shfl_xor_sync(0xffffffffu, lB, 2);
    const float invA = 1.0f / lA, invB = 1.0f / lB;

    const int rA = row0 + 16 * w + grp, rB = rA + 8;
    float* yA = y + (long)(b * SEQ + rA) * N_EMBD + hoff;
    float* yB = y + (long)(b * SEQ + rB) * N_EMBD + hoff;
    #pragma unroll
    for (int ni = 0; ni < 8; ni++) {
        const int c = ni * 8 + 2 * tg;
        *(float2*)(yA + c) = make_float2(oacc[ni][0] * invA, oacc[ni][1] * invA);
        *(float2*)(yB + c) = make_float2(oacc[ni][2] * invB, oacc[ni][3] * invB);
    }
}

// ---------------------------------------------------------------------------
extern "C" void kernel_launch(void* const* d_in, const int* in_sizes, int n_in,
                              void* d_out, int out_size)
{
    const float* x      = (const float*)d_in[0];
    const float* W_attn = (const float*)d_in[1];
    const float* b_attn = (const float*)d_in[2];
    const float* W_proj = (const float*)d_in[3];
    const float* b_proj = (const float*)d_in[4];
    float* out = (float*)d_out;

    float* qkv = nullptr;
    float* att = nullptr;
    cudaGetSymbolAddress((void**)&qkv, g_qkv);
    cudaGetSymbolAddress((void**)&att, g_att);

    static bool attr_set = false;
    if (!attr_set) {
        cudaFuncSetAttribute(flash_attn_tc,
                             cudaFuncAttributeMaxDynamicSharedMemorySize,
                             ATT_SMEM);
        attr_set = true;
    }

    const int M = BATCH * SEQ;  // 8192

    // 1) qkv = x @ W_attn + b_attn   [8192 x 3072]
    gemm_tf32_bias<<<dim3(C3 / BN, M / BM), 256>>>(
        x, W_attn, b_attn, qkv, M, C3, N_EMBD);

    // 2) causal flash attention (tensor core) -> att [8192 x 1024]
    flash_attn_tc<<<dim3(SEQ / QT, N_HEAD, BATCH), 128, ATT_SMEM>>>(qkv, att);

    // 3) out = att @ W_proj + b_proj  [8192 x 1024]
    gemm_tf32_bias<<<dim3(N_EMBD / BN, M / BM), 256>>>(
        att, W_proj, b_proj, out, M, N_EMBD, N_EMBD);
}

// round 16
// speedup vs baseline: 1.0700x; 1.0700x over previous
#include <cuda_runtime.h>
#include <cuda_bf16.h>
#include <cstdint>

#define N_EMBD 1024
#define N_HEAD 16
#define HEAD_DIM 64
#define BATCH 4
#define SEQ 2048
#define C3 (3 * N_EMBD)
#define MTOT (BATCH * SEQ)
#define KP 512  // bf16-pair count per 1024-elem row

// ---------------- scratch (no cudaMalloc allowed) ----------------
__device__ float g_qkv[MTOT * C3];          // fp32 qkv (attention input)
__device__ uint2 g_xp[MTOT * KP];           // x packed {hi-pair, lo-pair}
__device__ uint2 g_wap[C3 * KP];            // W_attn^T packed [3072][512]
__device__ uint2 g_wpp[N_EMBD * KP];        // W_proj^T packed [1024][512]
__device__ uint2 g_ap[MTOT * KP];           // att packed

__device__ __forceinline__ uint32_t f2tf32(float x) {
    uint32_t r;
    asm("cvt.rna.tf32.f32 %0, %1;" : "=r"(r) : "f"(x));
    return r;
}
__device__ __forceinline__ void mma_tf32(float c[4], uint32_t a0, uint32_t a1,
                                         uint32_t a2, uint32_t a3,
                                         uint32_t b0, uint32_t b1) {
    asm volatile(
        "mma.sync.aligned.m16n8k8.row.col.f32.tf32.tf32.f32 "
        "{%0,%1,%2,%3}, {%4,%5,%6,%7}, {%8,%9}, {%0,%1,%2,%3};"
        : "+f"(c[0]), "+f"(c[1]), "+f"(c[2]), "+f"(c[3])
        : "r"(a0), "r"(a1), "r"(a2), "r"(a3), "r"(b0), "r"(b1));
}
__device__ __forceinline__ void mma_bf16(float c[4], uint32_t a0, uint32_t a1,
                                         uint32_t a2, uint32_t a3,
                                         uint32_t b0, uint32_t b1) {
    asm volatile(
        "mma.sync.aligned.m16n8k16.row.col.f32.bf16.bf16.f32 "
        "{%0,%1,%2,%3}, {%4,%5,%6,%7}, {%8,%9}, {%0,%1,%2,%3};"
        : "+f"(c[0]), "+f"(c[1]), "+f"(c[2]), "+f"(c[3])
        : "r"(a0), "r"(a1), "r"(a2), "r"(a3), "r"(b0), "r"(b1));
}
// pack two floats -> bf16x2 (x in low half = even k element)
__device__ __forceinline__ uint32_t pack_bf16(float x, float y) {
    __nv_bfloat162 h = __floats2bfloat162_rn(x, y);
    return *(uint32_t*)&h;
}

// ---------------------------------------------------------------------------
// conversion kernels: fp32 -> packed bf16 hi/lo pairs
// ---------------------------------------------------------------------------
__global__ __launch_bounds__(256) void cvt_pack(const float* __restrict__ in,
                                                uint2* __restrict__ out, int npairs)
{
    const int i = blockIdx.x * 256 + threadIdx.x;
    if (i >= npairs) return;
    const float2 v = ((const float2*)in)[i];
    const float h0 = __bfloat162float(__float2bfloat16_rn(v.x));
    const float h1 = __bfloat162float(__float2bfloat16_rn(v.y));
    uint2 o;
    o.x = pack_bf16(h0, h1);
    o.y = pack_bf16(v.x - h0, v.y - h1);
    out[i] = o;
}

// W [K][N] fp32 -> out [N][K/2] packed pairs (transpose)
__global__ __launch_bounds__(256) void cvt_pack_T(const float* __restrict__ W,
                                                  uint2* __restrict__ out, int K, int N)
{
    __shared__ float t[32][33];
    const int n0 = blockIdx.x * 32, k0 = blockIdx.y * 32;
    const int tx = threadIdx.x & 31, ty = threadIdx.x >> 5;
    #pragma unroll
    for (int j = 0; j < 4; j++)
        t[ty + 8 * j][tx] = W[(long)(k0 + ty + 8 * j) * N + n0 + tx];
    __syncthreads();
    const int n_l = threadIdx.x >> 3, kp8 = threadIdx.x & 7;
    const int KPl = K / 2;
    #pragma unroll
    for (int pass = 0; pass < 2; pass++) {
        const int kp = kp8 + pass * 8;
        const float v0 = t[2 * kp][n_l], v1 = t[2 * kp + 1][n_l];
        const float h0 = __bfloat162float(__float2bfloat16_rn(v0));
        const float h1 = __bfloat162float(__float2bfloat16_rn(v1));
        uint2 o;
        o.x = pack_bf16(h0, h1);
        o.y = pack_bf16(v0 - h0, v1 - h1);
        out[(long)(n0 + n_l) * KPl + k0 / 2 + kp] = o;
    }
}

// ---------------------------------------------------------------------------
// bf16 hi/lo 3-mma tensor GEMM with bias: C[M,N] = A[M,K] @ Bt[N,K]^T + bias
// A, Bt packed as uint2{hi-pair, lo-pair}. 128x128 block, 8 warps 32x64 tile,
// k16 steps. Smem stride 20 uint2 (conflict-free LDS.64 fragment phases).
// ---------------------------------------------------------------------------
__global__ void __launch_bounds__(256, 2) gemm_bf16_bias(
    const uint2* __restrict__ A, const uint2* __restrict__ Bt,
    const float* __restrict__ bias, float* __restrict__ C,
    int M, int N, int kp)
{
    __shared__ uint2 As2[128 * 20];
    __shared__ uint2 Bs2[128 * 20];
    uint4* As4 = (uint4*)As2;
    uint4* Bs4 = (uint4*)Bs2;

    const int tid = threadIdx.x;
    const int wid = tid >> 5, lane = tid & 31;
    const int wm = wid & 3, wn = wid >> 2;
    const int tg = lane & 3, grp = lane >> 2;
    const int row0 = blockIdx.y * 128, col0 = blockIdx.x * 128;

    const int sr = tid >> 3, sc = tid & 7;   // staging: rows sr+32p, uint4 col sc
    const int kp4 = kp >> 1;                 // uint4 per row (256)
    const uint4* Ap = (const uint4*)A + (long)(row0 + sr) * kp4 + sc;
    const uint4* Bp = (const uint4*)Bt + (long)(col0 + sr) * kp4 + sc;

    float acc[2][8][4];
    #pragma unroll
    for (int mi = 0; mi < 2; mi++)
        #pragma unroll
        for (int ni = 0; ni < 8; ni++)
            #pragma unroll
            for (int e = 0; e < 4; e++) acc[mi][ni][e] = 0.0f;

    uint4 ra[4], rb[4];
    const int nt = kp / 16;  // 16 pairs (32 K-elems) per tile

    #pragma unroll
    for (int p = 0; p < 4; p++) {
        ra[p] = Ap[(long)(p * 32) * kp4];
        rb[p] = Bp[(long)(p * 32) * kp4];
    }

    for (int t = 0; t < nt; t++) {
        #pragma unroll
        for (int p = 0; p < 4; p++) {
            As4[(sr + p * 32) * 10 + sc] = ra[p];
            Bs4[(sr + p * 32) * 10 + sc] = rb[p];
        }
        __syncthreads();

        if (t + 1 < nt) {
            #pragma unroll
            for (int p = 0; p < 4; p++) {
                ra[p] = Ap[(long)(p * 32) * kp4 + (t + 1) * 8];
                rb[p] = Bp[(long)(p * 32) * kp4 + (t + 1) * 8];
            }
        }

        #pragma unroll
        for (int ks = 0; ks < 2; ks++) {
            const int kb = ks * 8;
            uint2 af[2][4];
            #pragma unroll
            for (int mi = 0; mi < 2; mi++) {
                const int row = wm * 32 + mi * 16 + grp;
                af[mi][0] = As2[row * 20 + kb + tg];
                af[mi][1] = As2[(row + 8) * 20 + kb + tg];
                af[mi][2] = As2[row * 20 + kb + tg + 4];
                af[mi][3] = As2[(row + 8) * 20 + kb + tg + 4];
            }
            #pragma unroll
            for (int ni = 0; ni < 8; ni++) {
                const int nr = wn * 64 + ni * 8 + grp;
                const uint2 v0 = Bs2[nr * 20 + kb + tg];
                const uint2 v1 = Bs2[nr * 20 + kb + tg + 4];
                #pragma unroll
                for (int mi = 0; mi < 2; mi++) {
                    mma_bf16(acc[mi][ni], af[mi][0].x, af[mi][1].x, af[mi][2].x,
                             af[mi][3].x, v0.x, v1.x);
                    mma_bf16(acc[mi][ni], af[mi][0].x, af[mi][1].x, af[mi][2].x,
                             af[mi][3].x, v0.y, v1.y);
                    mma_bf16(acc[mi][ni], af[mi][0].y, af[mi][1].y, af[mi][2].y,
                             af[mi][3].y, v0.x, v1.x);
                }
            }
        }
        __syncthreads();
    }

    #pragma unroll
    for (int mi = 0; mi < 2; mi++) {
        const long r0 = row0 + wm * 32 + mi * 16 + grp;
        const long r1 = r0 + 8;
        #pragma unroll
        for (int ni = 0; ni < 8; ni++) {
            const int c = col0 + wn * 64 + ni * 8 + tg * 2;
            const float bv0 = __ldg(&bias[c]);
            const float bv1 = __ldg(&bias[c + 1]);
            float2 o0 = make_float2(acc[mi][ni][0] + bv0, acc[mi][ni][1] + bv1);
            float2 o1 = make_float2(acc[mi][ni][2] + bv0, acc[mi][ni][3] + bv1);
            *(float2*)&C[r0 * N + c] = o0;
            *(float2*)&C[r1 * N + c] = o1;
        }
    }
}

// ---------------------------------------------------------------------------
// Tensor-core flash attention (causal) — proven round-12 version; epilogue
// writes packed bf16 hi/lo att pairs for the proj GEMM.
// ---------------------------------------------------------------------------
#define QT 64
#define KTILE 64
#define KC_S 36
#define VS_S 72
#define ATT_SMEM ((64 * KC_S * 2 + 64 * VS_S) * 4)  // 36864 B

__global__ __launch_bounds__(128) void flash_attn_tc(
    const float* __restrict__ qkv, uint2* __restrict__ yp)
{
    extern __shared__ __align__(16) float sm[];
    uint2* Kc = (uint2*)sm;
    float* Vs = sm + 64 * KC_S * 2;

    const int qt = blockIdx.x, h = blockIdx.y, b = blockIdx.z;
    const int tid = threadIdx.x;
    const int w = tid >> 5, lane = tid & 31;
    const int grp = lane >> 2, tg = lane & 3;
    const int row0 = qt * QT;
    const long base = (long)b * SEQ * C3;
    const int hoff = h * HEAD_DIM;

    uint32_t qhi[4][4], qlo[4][4];
    {
        const float* qA = qkv + base + (long)(row0 + 16 * w + grp) * C3 + hoff;
        const float* qB = qA + 8 * C3;
        #pragma unroll
        for (int ks = 0; ks < 4; ks++) {
            const int k0 = ks * 16 + 2 * tg;
            float fa0 = qA[k0] * 0.125f,     fa1 = qA[k0 + 1] * 0.125f;
            float fb0 = qB[k0] * 0.125f,     fb1 = qB[k0 + 1] * 0.125f;
            float fa2 = qA[k0 + 8] * 0.125f, fa3 = qA[k0 + 9] * 0.125f;
            float fb2 = qB[k0 + 8] * 0.125f, fb3 = qB[k0 + 9] * 0.125f;
            float ha0 = __bfloat162float(__float2bfloat16_rn(fa0));
            float ha1 = __bfloat162float(__float2bfloat16_rn(fa1));
            float hb0 = __bfloat162float(__float2bfloat16_rn(fb0));
            float hb1 = __bfloat162float(__float2bfloat16_rn(fb1));
            float ha2 = __bfloat162float(__float2bfloat16_rn(fa2));
            float ha3 = __bfloat162float(__float2bfloat16_rn(fa3));
            float hb2 = __bfloat162float(__float2bfloat16_rn(fb2));
            float hb3 = __bfloat162float(__float2bfloat16_rn(fb3));
            qhi[ks][0] = pack_bf16(ha0, ha1);
            qhi[ks][1] = pack_bf16(hb0, hb1);
            qhi[ks][2] = pack_bf16(ha2, ha3);
            qhi[ks][3] = pack_bf16(hb2, hb3);
            qlo[ks][0] = pack_bf16(fa0 - ha0, fa1 - ha1);
            qlo[ks][1] = pack_bf16(fb0 - hb0, fb1 - hb1);
            qlo[ks][2] = pack_bf16(fa2 - ha2, fa3 - ha3);
            qlo[ks][3] = pack_bf16(fb2 - hb2, fb3 - hb3);
        }
    }

    float oacc[8][4];
    #pragma unroll
    for (int ni = 0; ni < 8; ni++)
        #pragma unroll
        for (int e = 0; e < 4; e++) oacc[ni][e] = 0.0f;
    float mA = -1e30f, mB = -1e30f, lA = 0.0f, lB = 0.0f;

    for (int kt = 0; kt <= qt; kt++) {
        const int kc0 = kt * KTILE;
        __syncthreads();

        #pragma unroll
        for (int i = 0; i < 16; i++) {
            const int e = tid + i * 128;
            const int r = e >> 5, p = e & 31;
            const float2 kv = *(const float2*)(qkv + base + (long)(kc0 + r) * C3 +
                                               hoff + N_EMBD + 2 * p);
            const float h0 = __bfloat162float(__float2bfloat16_rn(kv.x));
            const float h1 = __bfloat162float(__float2bfloat16_rn(kv.y));
            uint2 val;
            val.x = pack_bf16(h0, h1);
            val.y = pack_bf16(kv.x - h0, kv.y - h1);
            Kc[r * KC_S + p] = val;
        }
        #pragma unroll
        for (int i = 0; i < 8; i++) {
            const int e = tid + i * 128;
            const int r = e >> 4, c4 = (e & 15) * 4;
            const float4 vv = *(const float4*)(qkv + base + (long)(kc0 + r) * C3 +
                                               hoff + 2 * N_EMBD + c4);
            float4 vt;
            vt.x = __uint_as_float(f2tf32(vv.x));
            vt.y = __uint_as_float(f2tf32(vv.y));
            vt.z = __uint_as_float(f2tf32(vv.z));
            vt.w = __uint_as_float(f2tf32(vv.w));
            *(float4*)&Vs[r * VS_S + c4] = vt;
        }
        __syncthreads();

        float sacc[8][4];
        #pragma unroll
        for (int ni = 0; ni < 8; ni++)
            #pragma unroll
            for (int e = 0; e < 4; e++) sacc[ni][e] = 0.0f;

        #pragma unroll
        for (int ks = 0; ks < 4; ks++) {
            #pragma unroll
            for (int ni = 0; ni < 8; ni++) {
                const int nb = ni * 8 + grp;
                const uint2 p0 = Kc[nb * KC_S + ks * 8 + tg];
                const uint2 p1 = Kc[nb * KC_S + ks * 8 + 4 + tg];
                mma_bf16(sacc[ni], qhi[ks][0], qhi[ks][1], qhi[ks][2], qhi[ks][3], p0.x, p1.x);
                mma_bf16(sacc[ni], qhi[ks][0], qhi[ks][1], qhi[ks][2], qhi[ks][3], p0.y, p1.y);
                mma_bf16(sacc[ni], qlo[ks][0], qlo[ks][1], qlo[ks][2], qlo[ks][3], p0.x, p1.x);
            }
        }

        if (kt == qt) {
            const int rA = row0 + 16 * w + grp, rB = rA + 8;
            #pragma unroll
            for (int ni = 0; ni < 8; ni++) {
                const int c0 = kc0 + ni * 8 + 2 * tg;
                if (c0 > rA) sacc[ni][0] = -1e30f;
                if (c0 + 1 > rA) sacc[ni][1] = -1e30f;
                if (c0 > rB) sacc[ni][2] = -1e30f;
                if (c0 + 1 > rB) sacc[ni][3] = -1e30f;
            }
        }

        float mtA = sacc[0][0], mtB = sacc[0][2];
        #pragma unroll
        for (int ni = 0; ni < 8; ni++) {
            mtA = fmaxf(mtA, fmaxf(sacc[ni][0], sacc[ni][1]));
            mtB = fmaxf(mtB, fmaxf(sacc[ni][2], sacc[ni][3]));
        }
        mtA = fmaxf(mtA, __shfl_xor_sync(0xffffffffu, mtA, 1));
        mtA = fmaxf(mtA, __shfl_xor_sync(0xffffffffu, mtA, 2));
        mtB = fmaxf(mtB, __shfl_xor_sync(0xffffffffu, mtB, 1));
        mtB = fmaxf(mtB, __shfl_xor_sync(0xffffffffu, mtB, 2));

        const float mnA = fmaxf(mA, mtA), mnB = fmaxf(mB, mtB);
        const float cA = __expf(mA - mnA), cB = __expf(mB - mnB);
        mA = mnA; mB = mnB;
        lA *= cA; lB *= cB;
        #pragma unroll
        for (int ni = 0; ni < 8; ni++) {
            oacc[ni][0] *= cA; oacc[ni][1] *= cA;
            oacc[ni][2] *= cB; oacc[ni][3] *= cB;
        }

        uint32_t up[8][4];
        float sumA = 0.0f, sumB = 0.0f;
        #pragma unroll
        for (int ni = 0; ni < 8; ni++) {
            const float p0 = __expf(sacc[ni][0] - mA);
            const float p1 = __expf(sacc[ni][1] - mA);
            const float p2 = __expf(sacc[ni][2] - mB);
            const float p3 = __expf(sacc[ni][3] - mB);
            sumA += p0 + p1; sumB += p2 + p3;
            up[ni][0] = f2tf32(p0); up[ni][1] = f2tf32(p1);
            up[ni][2] = f2tf32(p2); up[ni][3] = f2tf32(p3);
        }
        lA += sumA; lB += sumB;

        const int src0 = (lane & ~3) | (tg >> 1);
        const int src2 = src0 | 2;
        const bool odd = (tg & 1) != 0;
        #pragma unroll
        for (int ks = 0; ks < 8; ks++) {
            const int kb = ks * 8;
            const uint32_t w00 = __shfl_sync(0xffffffffu, up[ks][0], src0);
            const uint32_t w01 = __shfl_sync(0xffffffffu, up[ks][1], src0);
            const uint32_t w02 = __shfl_sync(0xffffffffu, up[ks][2], src0);
            const uint32_t w03 = __shfl_sync(0xffffffffu, up[ks][3], src0);
            const uint32_t w20 = __shfl_sync(0xffffffffu, up[ks][0], src2);
            const uint32_t w21 = __shfl_sync(0xffffffffu, up[ks][1], src2);
            const uint32_t w22 = __shfl_sync(0xffffffffu, up[ks][2], src2);
            const uint32_t w23 = __shfl_sync(0xffffffffu, up[ks][3], src2);
            const uint32_t a0 = odd ? w01 : w00;
            const uint32_t a1 = odd ? w03 : w02;
            const uint32_t a2 = odd ? w21 : w20;
            const uint32_t a3 = odd ? w23 : w22;
            #pragma unroll
            for (int ni = 0; ni < 8; ni++) {
                const uint32_t b0 = __float_as_uint(Vs[(kb + tg) * VS_S + ni * 8 + grp]);
                const uint32_t b1 = __float_as_uint(Vs[(kb + tg + 4) * VS_S + ni * 8 + grp]);
                mma_tf32(oacc[ni], a0, a1, a2, a3, b0, b1);
            }
        }
    }

    lA += __shfl_xor_sync(0xffffffffu, lA, 1);
    lA += __shfl_xor_sync(0xffffffffu, lA, 2);
    lB += __shfl_xor_sync(0xffffffffu, lB, 1);
    lB += __shfl_xor_sync(0xffffffffu, lB, 2);
    const float invA = 1.0f / lA, invB = 1.0f / lB;

    const int rA = row0 + 16 * w + grp, rB = rA + 8;
    const long pA = (long)(b * SEQ + rA) * KP + hoff / 2;
    const long pB = (long)(b * SEQ + rB) * KP + hoff / 2;
    #pragma unroll
    for (int ni = 0; ni < 8; ni++) {
        const float vA0 = oacc[ni][0] * invA, vA1 = oacc[ni][1] * invA;
        const float vB0 = oacc[ni][2] * invB, vB1 = oacc[ni][3] * invB;
        const float hA0 = __bfloat162float(__float2bfloat16_rn(vA0));
        const float hA1 = __bfloat162float(__float2bfloat16_rn(vA1));
        const float hB0 = __bfloat162float(__float2bfloat16_rn(vB0));
        const float hB1 = __bfloat162float(__float2bfloat16_rn(vB1));
        uint2 oA, oB;
        oA.x = pack_bf16(hA0, hA1);
        oA.y = pack_bf16(vA0 - hA0, vA1 - hA1);
        oB.x = pack_bf16(hB0, hB1);
        oB.y = pack_bf16(vB0 - hB0, vB1 - hB1);
        yp[pA + ni * 4 + tg] = oA;
        yp[pB + ni * 4 + tg] = oB;
    }
}

// ---------------------------------------------------------------------------
extern "C" void kernel_launch(void* const* d_in, const int* in_sizes, int n_in,
                              void* d_out, int out_size)
{
    const float* x      = (const float*)d_in[0];
    const float* W_attn = (const float*)d_in[1];
    const float* b_attn = (const float*)d_in[2];
    const float* W_proj = (const float*)d_in[3];
    const float* b_proj = (const float*)d_in[4];
    float* out = (float*)d_out;

    float* qkv; uint2 *xp, *wap, *wpp, *ap;
    cudaGetSymbolAddress((void**)&qkv, g_qkv);
    cudaGetSymbolAddress((void**)&xp, g_xp);
    cudaGetSymbolAddress((void**)&wap, g_wap);
    cudaGetSymbolAddress((void**)&wpp, g_wpp);
    cudaGetSymbolAddress((void**)&ap, g_ap);

    static bool attr_set = false;
    if (!attr_set) {
        cudaFuncSetAttribute(flash_attn_tc,
                             cudaFuncAttributeMaxDynamicSharedMemorySize, ATT_SMEM);
        attr_set = true;
    }

    // 0) pack inputs to bf16 hi/lo pairs
    cvt_pack<<<(MTOT * KP + 255) / 256, 256>>>(x, xp, MTOT * KP);
    cvt_pack_T<<<dim3(C3 / 32, N_EMBD / 32), 256>>>(W_attn, wap, N_EMBD, C3);
    cvt_pack_T<<<dim3(N_EMBD / 32, N_EMBD / 32), 256>>>(W_proj, wpp, N_EMBD, N_EMBD);

    // 1) qkv = x @ W_attn + b_attn  (bf16 hi/lo tensor GEMM)
    gemm_bf16_bias<<<dim3(C3 / 128, MTOT / 128), 256>>>(
        xp, wap, b_attn, qkv, MTOT, C3, KP);

    // 2) causal flash attention -> packed att
    flash_attn_tc<<<dim3(SEQ / QT, N_HEAD, BATCH), 128, ATT_SMEM>>>(qkv, ap);

    // 3) out = att @ W_proj + b_proj
    gemm_bf16_bias<<<dim3(N_EMBD / 128, MTOT / 128), 256>>>(
        ap, wpp, b_proj, out, MTOT, N_EMBD, KP);
}